// round 6
// baseline (speedup 1.0000x reference)
#include <cuda_runtime.h>

// Problem constants (B=4, 96^3 vol, 4^3 patches, E=768)
#define TOKENS   13824      // 24*24*24
#define MASKN    10368      // 75%
#define UNMASKN  3456
#define EDIM     768
#define KDIM     64
#define TT       16         // tokens per block
#define NTHREADS 768        // one thread per embed dim
#define NWARPS   (NTHREADS / 32)  // 24
#define UTILES   (UNMASKN / TT)   // 216
#define MTILES   (MASKN / TT)     // 648
#define BATCH    4
#define LOG2_1E4 13.287712379549449f

// positional-encoding table: g_pe[pos][c] = (c even ? sin : cos)(pos * 10000^-( (c>>1)/128 ))
__device__ float g_pe[24][256];

__device__ __forceinline__ unsigned long long pack2(float a) {
    unsigned long long r;
    asm("mov.b64 %0, {%1, %1};" : "=l"(r) : "f"(a));
    return r;
}
__device__ __forceinline__ void fma2(unsigned long long& acc,
                                     unsigned long long a, unsigned long long b) {
    asm("fma.rn.f32x2 %0, %1, %2, %0;" : "+l"(acc) : "l"(a), "l"(b));
}
__device__ __forceinline__ void unpack2(unsigned long long v, float& lo, float& hi) {
    asm("mov.b64 {%0, %1}, %2;" : "=f"(lo), "=f"(hi) : "l"(v));
}

// Blocks [0,24): fill pe table row = blockIdx.x. Blocks [24,..): write mask_idx tail.
__global__ __launch_bounds__(256)
void init_kernel(const int* __restrict__ perm, float* __restrict__ tail_out, int n_tail) {
    const int bi = blockIdx.x, tid = threadIdx.x;
    if (bi < 24) {
        const float invf = exp2f(-(float)(tid >> 1) * (LOG2_1E4 / 128.0f));
        float s, c;
        sincosf((float)bi * invf, &s, &c);
        g_pe[bi][tid] = (tid & 1) ? c : s;
    } else {
        const int i = (bi - 24) * 256 + tid;
        if (i < n_tail) tail_out[i] = (float)perm[i];
    }
}

// One block = 16 tokens x 768 dims, one THREAD per dim (fma2 accumulators over token pairs).
// 768 thr, ~40 regs -> 2 blocks/SM = 48 warps: fma-pipe-bound GEMM.
// Blocks [0, 864): unmask tokens (per batch). Blocks [864, 1512): mask tokens,
// computed once and written to all 4 batches (batch-invariant incl. LN).
__global__ __launch_bounds__(NTHREADS, 2)
void embed_kernel(const float* __restrict__ x,
                  const float* __restrict__ W,
                  const float* __restrict__ bias,
                  const float* __restrict__ mtok,
                  const float* __restrict__ gamma,
                  const float* __restrict__ beta,
                  const int*   __restrict__ perm,
                  float* __restrict__ out)
{
    __shared__ float ps[KDIM][TT];          // patch tile, k-major so token pairs are contiguous
    __shared__ int   sH[TT], sW[TT], sD[TT];
    __shared__ float redS[TT][NWARPS + 1], redQ[TT][NWARPS + 1];
    __shared__ float meanv[TT], rstdv[TT];

    const int tid = threadIdx.x;
    const int bi  = blockIdx.x;
    const bool is_mask = bi >= BATCH * UTILES;
    int b = 0, tile;
    if (!is_mask) { b = bi / UTILES; tile = bi % UTILES; }
    else          { tile = bi - BATCH * UTILES; }

    // ---- stage: gather 16 patch rows (64 floats each) into SMEM (threads 0-255) ----
    if (tid < 256) {
        const int tok = tid & 15;     // consecutive lanes -> consecutive tokens (conflict-free STS)
        const int seg = tid >> 4;     // 0..15 -> 4 floats each
        const int m   = tile * TT + tok;
        const int s   = is_mask ? perm[m] : perm[MASKN + m];
        const int h = s / 576, w = (s % 576) / 24, d = s % 24;
        if (seg == 0) { sH[tok] = h; sW[tok] = w; sD[tok] = d; }
        float4 v;
        if (!is_mask) {
            const int i = seg >> 2, j = seg & 3;
            const size_t xi = (((size_t)(b * 96 + 4 * h + i)) * 96 + (4 * w + j)) * 96 + 4 * d;
            v = *(const float4*)(x + xi);
        } else {
            v = *(const float4*)(mtok + (size_t)m * KDIM + seg * 4);
        }
        const int p = seg * 4;
        ps[p + 0][tok] = v.x; ps[p + 1][tok] = v.y;
        ps[p + 2][tok] = v.z; ps[p + 3][tok] = v.w;
    }
    __syncthreads();

    // ---- GEMM: thread owns embed dim `tid`; 8 f32x2 accumulators = 16 tokens ----
    unsigned long long acc[8];
    {
        const unsigned long long B0 = pack2(bias[tid]);
        #pragma unroll
        for (int t = 0; t < 8; t++) acc[t] = B0;
    }

    const float* wp = W + tid;
    #pragma unroll 4
    for (int k = 0; k < KDIM; k++) {
        const unsigned long long Wk = pack2(wp[(size_t)k * EDIM]);
        const ulonglong2* pp2 = (const ulonglong2*)ps[k];   // LDS.128 broadcast (4 tokens)
        #pragma unroll
        for (int q = 0; q < 4; q++) {
            const ulonglong2 pd = pp2[q];
            fma2(acc[2 * q],     pd.x, Wk);
            fma2(acc[2 * q + 1], pd.y, Wk);
        }
    }

    // ---- epilogue: unpack, + positional encoding from table ----
    float v[TT];
    #pragma unroll
    for (int t = 0; t < 8; t++) unpack2(acc[t], v[2 * t], v[2 * t + 1]);

    // thread's dim lives in one pe segment: tid<256 -> H, <512 -> W, else D
    const int* sposArr = (tid < 256) ? sH : (tid < 512) ? sW : sD;
    const int pecol = tid & 255;
    const int warp = tid >> 5, lane = tid & 31;

    #pragma unroll
    for (int t = 0; t < TT; t++) {
        v[t] += __ldg(&g_pe[sposArr[t]][pecol]);

        float sm = v[t];
        float sq = v[t] * v[t];
        #pragma unroll
        for (int off = 16; off > 0; off >>= 1) {
            sm += __shfl_xor_sync(0xffffffffu, sm, off);
            sq += __shfl_xor_sync(0xffffffffu, sq, off);
        }
        if (lane == 0) { redS[t][warp] = sm; redQ[t][warp] = sq; }
    }
    __syncthreads();

    if (tid < TT) {
        float sm = 0.f, sq = 0.f;
        #pragma unroll
        for (int wi = 0; wi < NWARPS; wi++) { sm += redS[tid][wi]; sq += redQ[tid][wi]; }
        const float mn = sm * (1.0f / (float)EDIM);
        const float vr = sq * (1.0f / (float)EDIM) - mn * mn;
        meanv[tid] = mn;
        rstdv[tid] = rsqrtf(vr + 0.001f);
    }
    __syncthreads();

    const float g0  = gamma[tid];
    const float be0 = beta[tid];

    if (!is_mask) {
        float* o = out + ((size_t)b * TOKENS + (size_t)tile * TT) * EDIM + tid;
        #pragma unroll
        for (int t = 0; t < TT; t++) {
            o[(size_t)t * EDIM] = (v[t] - meanv[t]) * rstdv[t] * g0 + be0;
        }
    } else {
        float* o = out + ((size_t)UNMASKN + (size_t)tile * TT) * EDIM + tid;
        const size_t bstride = (size_t)TOKENS * EDIM;
        #pragma unroll
        for (int t = 0; t < TT; t++) {
            const float r = (v[t] - meanv[t]) * rstdv[t] * g0 + be0;
            float* op = o + (size_t)t * EDIM;
            op[0]           = r;
            op[bstride]     = r;
            op[2 * bstride] = r;
            op[3 * bstride] = r;
        }
    }
}

extern "C" void kernel_launch(void* const* d_in, const int* in_sizes, int n_in,
                              void* d_out, int out_size) {
    const float* x     = (const float*)d_in[0];
    const float* W     = (const float*)d_in[1];
    const float* bias  = (const float*)d_in[2];
    const float* mtok  = (const float*)d_in[3];
    const float* gamma = (const float*)d_in[4];
    const float* beta  = (const float*)d_in[5];
    const int*   perm  = (const int*)d_in[6];
    float* out = (float*)d_out;

    const long long main_elems = (long long)BATCH * TOKENS * EDIM;  // 42,467,328
    const long long extra = (long long)out_size - main_elems;       // expected 10368 (mask_idx)
    const int n_tail = extra > 0 ? (int)extra : 0;
    const int tail_blocks = (n_tail + 255) / 256;

    // init: pe table (24 blocks) + mask_idx tail writes
    init_kernel<<<24 + tail_blocks, 256>>>(perm, out + main_elems, n_tail);

    embed_kernel<<<BATCH * UTILES + MTILES, NTHREADS>>>(x, W, bias, mtok, gamma, beta, perm, out);
}

// round 7
// speedup vs baseline: 1.1463x; 1.1463x over previous
#include <cuda_runtime.h>

// Problem constants (B=4, 96^3 vol, 4^3 patches, E=768)
#define TOKENS   13824      // 24*24*24
#define MASKN    10368      // 75%
#define UNMASKN  3456
#define EDIM     768
#define KDIM     64
#define TT       16         // tokens per block
#define NTHREADS 192        // 192 threads x 4 consecutive dims = 768
#define UTILES   (UNMASKN / TT)   // 216
#define MTILES   (MASKN / TT)     // 648
#define BATCH    4
#define LOG2_1E4 13.287712379549449f

// positional-encoding table: g_pe[pos][c] = (c even ? sin : cos)(pos * 10000^-( (c>>1)/128 ))
__device__ float g_pe[24][256];

__device__ __forceinline__ unsigned long long pack2(float a) {
    unsigned long long r;
    asm("mov.b64 %0, {%1, %1};" : "=l"(r) : "f"(a));
    return r;
}
__device__ __forceinline__ void fma2(unsigned long long& acc,
                                     unsigned long long a, unsigned long long b) {
    asm("fma.rn.f32x2 %0, %1, %2, %0;" : "+l"(acc) : "l"(a), "l"(b));
}
__device__ __forceinline__ void unpack2(unsigned long long v, float& lo, float& hi) {
    asm("mov.b64 {%0, %1}, %2;" : "=f"(lo), "=f"(hi) : "l"(v));
}

// Blocks [0,24): fill pe table row = blockIdx.x. Blocks [24,..): write mask_idx tail.
__global__ __launch_bounds__(256)
void init_kernel(const int* __restrict__ perm, float* __restrict__ tail_out, int n_tail) {
    const int bi = blockIdx.x, tid = threadIdx.x;
    if (bi < 24) {
        const float invf = exp2f(-(float)(tid >> 1) * (LOG2_1E4 / 128.0f));
        float s, c;
        sincosf((float)bi * invf, &s, &c);
        g_pe[bi][tid] = (tid & 1) ? c : s;
    } else {
        const int i = (bi - 24) * 256 + tid;
        if (i < n_tail) tail_out[i] = (float)perm[i];
    }
}

// One block = 16 tokens x 768 dims. Thread owns dims 4*tid..4*tid+3 (one pe segment).
// 4 blocks/SM (reg cap 85) -> 24 warps/SM at the measured-best L1/fma balance.
// Blocks [0, 864): unmask tokens per batch. Blocks [864, 1512): mask tokens,
// computed once, written to all 4 batches (batch-invariant incl. LN).
__global__ __launch_bounds__(NTHREADS, 4)
void embed_kernel(const float* __restrict__ x,
                  const float* __restrict__ W,
                  const float* __restrict__ bias,
                  const float* __restrict__ mtok,
                  const float* __restrict__ gamma,
                  const float* __restrict__ beta,
                  const int*   __restrict__ perm,
                  float* __restrict__ out)
{
    __shared__ float ps[KDIM][TT];          // patch tile, k-major; token pairs contiguous
    __shared__ int   sH[TT], sW[TT], sD[TT];
    __shared__ float redS[TT][6], redQ[TT][6];
    __shared__ float meanv[TT], rstdv[TT];

    const int tid = threadIdx.x;
    const int bi  = blockIdx.x;
    const bool is_mask = bi >= BATCH * UTILES;
    int b = 0, tile;
    if (!is_mask) { b = bi / UTILES; tile = bi % UTILES; }
    else          { tile = bi - BATCH * UTILES; }

    // ---- stage: gather 16 patch rows (64 floats each) into SMEM ----
    for (int it = tid; it < TT * 16; it += NTHREADS) {
        const int tok = it & 15;      // consecutive lanes -> consecutive tokens (low-conflict STS)
        const int seg = it >> 4;      // 0..15 -> 4 floats each
        const int m   = tile * TT + tok;
        const int s   = is_mask ? perm[m] : perm[MASKN + m];
        const int h = s / 576, w = (s % 576) / 24, d = s % 24;
        if (seg == 0) { sH[tok] = h; sW[tok] = w; sD[tok] = d; }
        float4 v;
        if (!is_mask) {
            const int i = seg >> 2, j = seg & 3;
            const size_t xi = (((size_t)(b * 96 + 4 * h + i)) * 96 + (4 * w + j)) * 96 + 4 * d;
            v = *(const float4*)(x + xi);
        } else {
            v = *(const float4*)(mtok + (size_t)m * KDIM + seg * 4);
        }
        const int p = seg * 4;
        ps[p + 0][tok] = v.x; ps[p + 1][tok] = v.y;
        ps[p + 2][tok] = v.z; ps[p + 3][tok] = v.w;
    }
    __syncthreads();

    // ---- GEMM: thread owns 4 consecutive dims; accumulators = token pairs (f32x2) ----
    unsigned long long a0[8], a1[8], a2[8], a3[8];
    {
        const float4 b4 = *((const float4*)bias + tid);
        const unsigned long long B0 = pack2(b4.x), B1 = pack2(b4.y),
                                 B2 = pack2(b4.z), B3 = pack2(b4.w);
        #pragma unroll
        for (int t = 0; t < 8; t++) { a0[t] = B0; a1[t] = B1; a2[t] = B2; a3[t] = B3; }
    }

    const float4* wp4 = (const float4*)W + tid;
    #pragma unroll 2
    for (int k = 0; k < KDIM; k++) {
        const float4 w4 = wp4[k * (EDIM / 4)];
        const unsigned long long W0 = pack2(w4.x), W1 = pack2(w4.y),
                                 W2 = pack2(w4.z), W3 = pack2(w4.w);
        const ulonglong2* pp2 = (const ulonglong2*)ps[k];   // broadcast LDS.128
        #pragma unroll
        for (int q = 0; q < 4; q++) {
            const ulonglong2 pd = pp2[q];
            fma2(a0[2 * q],     pd.x, W0);
            fma2(a1[2 * q],     pd.x, W1);
            fma2(a2[2 * q],     pd.x, W2);
            fma2(a3[2 * q],     pd.x, W3);
            fma2(a0[2 * q + 1], pd.y, W0);
            fma2(a1[2 * q + 1], pd.y, W1);
            fma2(a2[2 * q + 1], pd.y, W2);
            fma2(a3[2 * q + 1], pd.y, W3);
        }
    }

    // ---- epilogue ----
    float v0[TT], v1[TT], v2[TT], v3[TT];
    #pragma unroll
    for (int t = 0; t < 8; t++) {
        unpack2(a0[t], v0[2 * t], v0[2 * t + 1]);
        unpack2(a1[t], v1[2 * t], v1[2 * t + 1]);
        unpack2(a2[t], v2[2 * t], v2[2 * t + 1]);
        unpack2(a3[t], v3[2 * t], v3[2 * t + 1]);
    }

    // thread's 4 dims live in exactly one pe segment: tid<64 -> H, <128 -> W, else D
    const int* sposArr = (tid < 64) ? sH : (tid < 128) ? sW : sD;
    const int pecol = (tid & 63) * 4;
    const int warp = tid >> 5, lane = tid & 31;

    #pragma unroll
    for (int t = 0; t < TT; t++) {
        const float4 pe = __ldg((const float4*)&g_pe[sposArr[t]][pecol]);
        v0[t] += pe.x; v1[t] += pe.y; v2[t] += pe.z; v3[t] += pe.w;

        float sm = v0[t] + v1[t] + v2[t] + v3[t];
        float sq = v0[t] * v0[t] + v1[t] * v1[t] + v2[t] * v2[t] + v3[t] * v3[t];
        #pragma unroll
        for (int off = 16; off > 0; off >>= 1) {
            sm += __shfl_xor_sync(0xffffffffu, sm, off);
            sq += __shfl_xor_sync(0xffffffffu, sq, off);
        }
        if (lane == 0) { redS[t][warp] = sm; redQ[t][warp] = sq; }
    }
    __syncthreads();

    if (tid < TT) {
        float sm = 0.f, sq = 0.f;
        #pragma unroll
        for (int wi = 0; wi < 6; wi++) { sm += redS[tid][wi]; sq += redQ[tid][wi]; }
        const float mn = sm * (1.0f / (float)EDIM);
        const float vr = sq * (1.0f / (float)EDIM) - mn * mn;
        meanv[tid] = mn;
        rstdv[tid] = rsqrtf(vr + 0.001f);
    }
    __syncthreads();

    const float4 g4  = *((const float4*)gamma + tid);
    const float4 be4 = *((const float4*)beta + tid);

    if (!is_mask) {
        float4* o = (float4*)(out + ((size_t)b * TOKENS + (size_t)tile * TT) * EDIM) + tid;
        #pragma unroll
        for (int t = 0; t < TT; t++) {
            const float mn = meanv[t], rs = rstdv[t];
            float4 r;
            r.x = (v0[t] - mn) * rs * g4.x + be4.x;
            r.y = (v1[t] - mn) * rs * g4.y + be4.y;
            r.z = (v2[t] - mn) * rs * g4.z + be4.z;
            r.w = (v3[t] - mn) * rs * g4.w + be4.w;
            o[(size_t)t * (EDIM / 4)] = r;
        }
    } else {
        float4* o = (float4*)(out + ((size_t)UNMASKN + (size_t)tile * TT) * EDIM) + tid;
        const size_t bstride = (size_t)TOKENS * (EDIM / 4);
        #pragma unroll
        for (int t = 0; t < TT; t++) {
            const float mn = meanv[t], rs = rstdv[t];
            float4 r;
            r.x = (v0[t] - mn) * rs * g4.x + be4.x;
            r.y = (v1[t] - mn) * rs * g4.y + be4.y;
            r.z = (v2[t] - mn) * rs * g4.z + be4.z;
            r.w = (v3[t] - mn) * rs * g4.w + be4.w;
            float4* op = o + (size_t)t * (EDIM / 4);
            op[0]           = r;
            op[bstride]     = r;
            op[2 * bstride] = r;
            op[3 * bstride] = r;
        }
    }
}

extern "C" void kernel_launch(void* const* d_in, const int* in_sizes, int n_in,
                              void* d_out, int out_size) {
    const float* x     = (const float*)d_in[0];
    const float* W     = (const float*)d_in[1];
    const float* bias  = (const float*)d_in[2];
    const float* mtok  = (const float*)d_in[3];
    const float* gamma = (const float*)d_in[4];
    const float* beta  = (const float*)d_in[5];
    const int*   perm  = (const int*)d_in[6];
    float* out = (float*)d_out;

    const long long main_elems = (long long)BATCH * TOKENS * EDIM;  // 42,467,328
    const long long extra = (long long)out_size - main_elems;       // expected 10368 (mask_idx)
    const int n_tail = extra > 0 ? (int)extra : 0;
    const int tail_blocks = (n_tail + 255) / 256;

    // init: pe table (24 blocks) + mask_idx tail writes
    init_kernel<<<24 + tail_blocks, 256>>>(perm, out + main_elems, n_tail);

    embed_kernel<<<BATCH * UTILES + MTILES, NTHREADS>>>(x, W, bias, mtok, gamma, beta, perm, out);
}

// round 8
// speedup vs baseline: 1.3378x; 1.1670x over previous
#include <cuda_runtime.h>
#include <cuda_bf16.h>

// Problem constants (B=4, 96^3 vol, 4^3 patches, E=768)
#define TOKENS   13824
#define MASKN    10368
#define UNMASKN  3456
#define EDIM     768
#define KDIM     64
#define KPAIRS   96            // K' = 3*KDIM = 192 bf16 -> 96 bf16x2 pairs
#define TT       32            // tokens per block
#define NTHREADS 768
#define NWARPS   24
#define UT32     (UNMASKN / TT)   // 108
#define MT32     (MASKN / TT)     // 324
#define BATCH    4
#define AROW     99            // padded A' row stride (uint32 words)
#define BROW     776           // padded B stage row stride (uint32 words)
#define LOG2_1E4 13.287712379549449f

// positional-encoding table: g_pe[pos][c] = (c even ? sin : cos)(pos * 10000^-((c>>1)/128))
__device__ float g_pe[24][256];
// split weights, expanded K'=192, packed bf16x2 pairs: g_B2[p][e] = (B'[2p][e], B'[2p+1][e])
// B'[k'][e]: k'=3m+r, r==1 -> Wlo[m][e], else Whi[m][e]
__device__ unsigned int g_B2[KPAIRS][EDIM];

__device__ __forceinline__ unsigned int bf16pair(float lo, float hi) {
    __nv_bfloat162 h = __floats2bfloat162_rn(lo, hi);   // .x = lo half
    return *reinterpret_cast<unsigned int*>(&h);
}

__device__ __forceinline__ void mma_bf16(float* c,
    unsigned int a0, unsigned int a1, unsigned int a2, unsigned int a3,
    unsigned int b0, unsigned int b1) {
    asm volatile(
        "mma.sync.aligned.m16n8k16.row.col.f32.bf16.bf16.f32 "
        "{%0,%1,%2,%3}, {%4,%5,%6,%7}, {%8,%9}, {%0,%1,%2,%3};"
        : "+f"(c[0]), "+f"(c[1]), "+f"(c[2]), "+f"(c[3])
        : "r"(a0), "r"(a1), "r"(a2), "r"(a3), "r"(b0), "r"(b1));
}

// Blocks [0,24): pe table. Blocks [24,..): mask_idx tail.
__global__ __launch_bounds__(256)
void init_pe_kernel(const int* __restrict__ perm, float* __restrict__ tail_out, int n_tail) {
    const int bi = blockIdx.x, tid = threadIdx.x;
    if (bi < 24) {
        const float invf = exp2f(-(float)(tid >> 1) * (LOG2_1E4 / 128.0f));
        float s, c;
        sincosf((float)bi * invf, &s, &c);
        g_pe[bi][tid] = (tid & 1) ? c : s;
    } else {
        const int i = (bi - 24) * 256 + tid;
        if (i < n_tail) tail_out[i] = (float)perm[i];
    }
}

// Precompute split W into packed bf16x2 pairs. 96*768/256 = 288 blocks.
__global__ __launch_bounds__(256)
void init_w_kernel(const float* __restrict__ W) {
    const int idx = blockIdx.x * 256 + threadIdx.x;
    const int p = idx / EDIM, e = idx % EDIM;
    float v[2];
    #pragma unroll
    for (int i = 0; i < 2; i++) {
        const int kp = 2 * p + i, m = kp / 3, r = kp - 3 * m;
        const float wv = W[m * EDIM + e];
        const float wh = __bfloat162float(__float2bfloat16_rn(wv));
        v[i] = (r == 1) ? (wv - wh) : wv;   // bf16pair rounds
    }
    g_B2[p][e] = bf16pair(v[0], v[1]);
}

// One block: 32 tokens x 768 dims via bf16-split tensor-core MMA + fused bias/pe/LN.
// 24 warps = 2 token-bands(16) x 12 dim-groups(64). Blocks [0, 4*108): unmask per batch.
// Blocks [432, 756): mask tokens computed once, written to all 4 batches.
__global__ __launch_bounds__(NTHREADS, 1)
void embed_kernel(const float* __restrict__ x,
                  const float* __restrict__ bias,
                  const float* __restrict__ mtok,
                  const float* __restrict__ gamma,
                  const float* __restrict__ beta,
                  const int*   __restrict__ perm,
                  float* __restrict__ out)
{
    __shared__ __align__(16) unsigned int As[TT][AROW];   // A' packed bf16x2, token-major
    __shared__ __align__(16) unsigned int Bs[8][BROW];    // B' stage for one k-step
    __shared__ int   sH[TT], sW[TT], sD[TT];
    __shared__ float redS[TT][13], redQ[TT][13];
    __shared__ float meanv[TT], rstdv[TT];

    const int tid  = threadIdx.x;
    const int lane = tid & 31;
    const int w    = tid >> 5;
    const int g    = lane >> 2;      // groupID (row within m16)
    const int tg   = lane & 3;       // thread in group
    const int band = w / 12;         // token band (16 tokens)
    const int dg   = w % 12;         // dim group (64 dims)

    const int bi = blockIdx.x;
    const bool is_mask = bi >= BATCH * UT32;
    int b = 0, tile;
    if (!is_mask) { b = bi / UT32; tile = bi % UT32; }
    else          { tile = bi - BATCH * UT32; }

    // ---- acc init with bias (c0,c1 = row g; c2,c3 = row g+8; cols ebase+8j, +1) ----
    const int ebase = dg * 64 + 2 * tg;
    float acc[8][4];
    #pragma unroll
    for (int j = 0; j < 8; j++) {
        const float2 bb = *(const float2*)(bias + ebase + 8 * j);
        acc[j][0] = bb.x; acc[j][1] = bb.y; acc[j][2] = bb.x; acc[j][3] = bb.y;
    }

    // ---- stage A': gather 32 patch rows, bf16-split, expand K'=192 ----
    if (tid < 512) {
        const int tok = tid & 31;
        const int seg = tid >> 5;     // 0..15, 4 k-values each
        const int m   = tile * TT + tok;
        const int s   = is_mask ? perm[m] : perm[MASKN + m];
        const int h = s / 576, wq = (s % 576) / 24, d = s % 24;
        if (seg == 0) { sH[tok] = h; sW[tok] = wq; sD[tok] = d; }
        float4 v;
        if (!is_mask) {
            const int i = seg >> 2, j = seg & 3;
            const size_t xi = (((size_t)(b * 96 + 4 * h + i)) * 96 + (4 * wq + j)) * 96 + 4 * d;
            v = *(const float4*)(x + xi);
        } else {
            v = *(const float4*)(mtok + (size_t)m * KDIM + seg * 4);
        }
        // split each float: A' roles per k: [h, h, l]; pack pairs (even k' low half)
        const float f0 = v.x, f1 = v.y, f2 = v.z, f3 = v.w;
        const float h0 = __bfloat162float(__float2bfloat16_rn(f0));
        const float h1 = __bfloat162float(__float2bfloat16_rn(f1));
        const float h2 = __bfloat162float(__float2bfloat16_rn(f2));
        const float h3 = __bfloat162float(__float2bfloat16_rn(f3));
        unsigned int* ar = &As[tok][6 * seg];
        ar[0] = bf16pair(f0,      f0);        // (Ah0, Ah0)
        ar[1] = bf16pair(f0 - h0, f1);        // (Al0, Ah1)
        ar[2] = bf16pair(f1,      f1 - h1);   // (Ah1, Al1)
        ar[3] = bf16pair(f2,      f2);        // (Ah2, Ah2)
        ar[4] = bf16pair(f2 - h2, f3);        // (Al2, Ah3)
        ar[5] = bf16pair(f3,      f3 - h3);   // (Ah3, Al3)
    }

    // ---- B stage prologue for ks = 0 ----
    {
        const int i0 = tid, i1 = tid + 768;   // 1536 uint4-chunks: rows 8 x 192 chunks
        const uint4 s0 = *(const uint4*)&g_B2[i0 / 192][(i0 % 192) * 4];
        const uint4 s1 = *(const uint4*)&g_B2[i1 / 192][(i1 % 192) * 4];
        *(uint4*)&Bs[i0 / 192][(i0 % 192) * 4] = s0;
        *(uint4*)&Bs[i1 / 192][(i1 % 192) * 4] = s1;
    }
    __syncthreads();

    // ---- GEMM main loop: 12 k-steps of m16n8k16 ----
    const int arow0 = band * 16 + g;
    #pragma unroll 1
    for (int ks = 0; ks < 12; ks++) {
        uint4 nx0, nx1;
        if (ks < 11) {
            const int i0 = tid, i1 = tid + 768;
            nx0 = *(const uint4*)&g_B2[8 * (ks + 1) + i0 / 192][(i0 % 192) * 4];
            nx1 = *(const uint4*)&g_B2[8 * (ks + 1) + i1 / 192][(i1 % 192) * 4];
        }
        const unsigned int a0 = As[arow0][8 * ks + tg];
        const unsigned int a1 = As[arow0 + 8][8 * ks + tg];
        const unsigned int a2 = As[arow0][8 * ks + tg + 4];
        const unsigned int a3 = As[arow0 + 8][8 * ks + tg + 4];
        const int bcol = dg * 64 + g;
        #pragma unroll
        for (int j = 0; j < 8; j++) {
            const unsigned int b0 = Bs[tg][bcol + 8 * j];
            const unsigned int b1 = Bs[tg + 4][bcol + 8 * j];
            mma_bf16(acc[j], a0, a1, a2, a3, b0, b1);
        }
        __syncthreads();
        if (ks < 11) {
            const int i0 = tid, i1 = tid + 768;
            *(uint4*)&Bs[i0 / 192][(i0 % 192) * 4] = nx0;
            *(uint4*)&Bs[i1 / 192][(i1 % 192) * 4] = nx1;
            __syncthreads();
        }
    }

    // ---- epilogue: + positional encoding, LN stats ----
    const int t0 = band * 16 + g, t1 = t0 + 8;
    const int* sposArr = (dg < 4) ? sH : (dg < 8) ? sW : sD;
    const int pos0 = sposArr[t0], pos1 = sposArr[t1];
    const int pecol = (dg & 3) * 64 + 2 * tg;

    float s0 = 0.f, q0 = 0.f, s1 = 0.f, q1 = 0.f;
    #pragma unroll
    for (int j = 0; j < 8; j++) {
        const float2 p0 = *(const float2*)&g_pe[pos0][pecol + 8 * j];
        const float2 p1 = *(const float2*)&g_pe[pos1][pecol + 8 * j];
        acc[j][0] += p0.x; acc[j][1] += p0.y;
        acc[j][2] += p1.x; acc[j][3] += p1.y;
        s0 += acc[j][0] + acc[j][1];
        q0 += acc[j][0] * acc[j][0] + acc[j][1] * acc[j][1];
        s1 += acc[j][2] + acc[j][3];
        q1 += acc[j][2] * acc[j][2] + acc[j][3] * acc[j][3];
    }
    #pragma unroll
    for (int off = 1; off <= 2; off <<= 1) {
        s0 += __shfl_xor_sync(0xffffffffu, s0, off);
        q0 += __shfl_xor_sync(0xffffffffu, q0, off);
        s1 += __shfl_xor_sync(0xffffffffu, s1, off);
        q1 += __shfl_xor_sync(0xffffffffu, q1, off);
    }
    if (tg == 0) {
        redS[t0][dg] = s0; redQ[t0][dg] = q0;
        redS[t1][dg] = s1; redQ[t1][dg] = q1;
    }
    __syncthreads();

    if (tid < TT) {
        float sm = 0.f, sq = 0.f;
        #pragma unroll
        for (int wi = 0; wi < 12; wi++) { sm += redS[tid][wi]; sq += redQ[tid][wi]; }
        const float mn = sm * (1.0f / (float)EDIM);
        const float vr = sq * (1.0f / (float)EDIM) - mn * mn;
        meanv[tid] = mn;
        rstdv[tid] = rsqrtf(vr + 0.001f);
    }
    __syncthreads();

    const float mn0 = meanv[t0], rs0 = rstdv[t0];
    const float mn1 = meanv[t1], rs1 = rstdv[t1];

    if (!is_mask) {
        float* o0 = out + ((size_t)b * TOKENS + (size_t)tile * TT + t0) * EDIM;
        float* o1 = out + ((size_t)b * TOKENS + (size_t)tile * TT + t1) * EDIM;
        #pragma unroll
        for (int j = 0; j < 8; j++) {
            const int e = ebase + 8 * j;
            const float2 gm = *(const float2*)(gamma + e);
            const float2 bt = *(const float2*)(beta + e);
            float2 r0, r1;
            r0.x = (acc[j][0] - mn0) * rs0 * gm.x + bt.x;
            r0.y = (acc[j][1] - mn0) * rs0 * gm.y + bt.y;
            r1.x = (acc[j][2] - mn1) * rs1 * gm.x + bt.x;
            r1.y = (acc[j][3] - mn1) * rs1 * gm.y + bt.y;
            *(float2*)(o0 + e) = r0;
            *(float2*)(o1 + e) = r1;
        }
    } else {
        float* o0 = out + ((size_t)UNMASKN + (size_t)tile * TT + t0) * EDIM;
        float* o1 = out + ((size_t)UNMASKN + (size_t)tile * TT + t1) * EDIM;
        const size_t bstride = (size_t)TOKENS * EDIM;
        #pragma unroll
        for (int j = 0; j < 8; j++) {
            const int e = ebase + 8 * j;
            const float2 gm = *(const float2*)(gamma + e);
            const float2 bt = *(const float2*)(beta + e);
            float2 r0, r1;
            r0.x = (acc[j][0] - mn0) * rs0 * gm.x + bt.x;
            r0.y = (acc[j][1] - mn0) * rs0 * gm.y + bt.y;
            r1.x = (acc[j][2] - mn1) * rs1 * gm.x + bt.x;
            r1.y = (acc[j][3] - mn1) * rs1 * gm.y + bt.y;
            #pragma unroll
            for (int bb = 0; bb < BATCH; bb++) {
                *(float2*)(o0 + bb * bstride + e) = r0;
                *(float2*)(o1 + bb * bstride + e) = r1;
            }
        }
    }
}

extern "C" void kernel_launch(void* const* d_in, const int* in_sizes, int n_in,
                              void* d_out, int out_size) {
    const float* x     = (const float*)d_in[0];
    const float* W     = (const float*)d_in[1];
    const float* bias  = (const float*)d_in[2];
    const float* mtok  = (const float*)d_in[3];
    const float* gamma = (const float*)d_in[4];
    const float* beta  = (const float*)d_in[5];
    const int*   perm  = (const int*)d_in[6];
    float* out = (float*)d_out;

    const long long main_elems = (long long)BATCH * TOKENS * EDIM;  // 42,467,328
    const long long extra = (long long)out_size - main_elems;       // expected 10368 (mask_idx)
    const int n_tail = extra > 0 ? (int)extra : 0;
    const int tail_blocks = (n_tail + 255) / 256;

    init_pe_kernel<<<24 + tail_blocks, 256>>>(perm, out + main_elems, n_tail);
    init_w_kernel<<<(KPAIRS * EDIM) / 256, 256>>>(W);   // 288 blocks

    embed_kernel<<<BATCH * UT32 + MT32, NTHREADS>>>(x, bias, mtok, gamma, beta, perm, out);
}